// round 16
// baseline (speedup 1.0000x reference)
#include <cuda_runtime.h>
#include <cuda_fp16.h>
#include <cstdint>

// ---------------- problem constants ----------------
#define BATCH     32
#define LEN       220500
#define HOP       512
#define PADW      1024
#define FREQ      1025
#define NFRAMES   431
#define NBT       (BATCH * NFRAMES)     // 13792
#define NPAD      13824                 // 216 * 64
#define NFFT      2048
#define MLDA      512                   // GEMM M (k-bins 0..511)
#define KP        256                   // kp rows per parity half
#define NKT2      32                    // total kp-tiles (16 per parity)
#define ASTR      136                   // A smem row stride (u32) ≡8 mod 32
#define BSTR      72                    // B smem row stride (u32) ≡8 mod 32
#define ASZ       (16 * ASTR)           // 2176 words
#define BSZ       (16 * BSTR)           // 1152 words
#define STAGE_WORDS (ASZ + BSZ)         // 3328 u32 (13312 B)
#define STAGES    5
#define SMEM_BYTES (STAGES * STAGE_WORDS * 4)    // 66560 B (2 CTAs/SM)

// ---------------- device scratch ----------------
// half2-packed along K: word [h][kp][col] = {val(k=2kp), val(k=2kp+1)}
// h=0 <-> odd j (even i=j+1, "P+"), h=1 <-> even j ("P-"); rows 0..511 linear
__device__ unsigned g_W16c[2 * KP * MLDA];
__device__ unsigned g_W16s[2 * KP * MLDA];
__device__ unsigned g_U16 [2 * KP * NPAD];
__device__ unsigned g_V16 [2 * KP * NPAD];

__device__ __forceinline__ void cpa16(uint32_t s, const void* g) {
    asm volatile("cp.async.cg.shared.global [%0], [%1], 16;" :: "r"(s), "l"(g));
}
__device__ __forceinline__ void cpa_commit() {
    asm volatile("cp.async.commit_group;" ::: "memory");
}
template <int N>
__device__ __forceinline__ void cpa_wait() {
    asm volatile("cp.async.wait_group %0;" :: "n"(N) : "memory");
}
__device__ __forceinline__ unsigned packh2(float lo, float hi) {
    __half2 h = __floats2half2_rn(lo, hi);
    return *(unsigned*)&h;
}

// ---------------- kernel 1: weight transpose + fp16 K-pair pack ----------------
__global__ void __launch_bounds__(256) wprep_kernel(const float* __restrict__ wcos,
                                                    const float* __restrict__ wsin) {
    __shared__ float sc[32][33];
    __shared__ float ss[32][33];
    const int kt = blockIdx.y * 32;
    const int jt = blockIdx.x * 32;
    const int tx = threadIdx.x & 31;
    const int ty = threadIdx.x >> 5;
#pragma unroll
    for (int tt = 0; tt < 4; ++tt) {
        int kl = ty * 4 + tt;
        size_t src = (size_t)(kt + kl) * NFFT + jt + tx + 1;
        sc[kl][tx] = wcos[src];
        ss[kl][tx] = wsin[src];
    }
    __syncthreads();
#pragma unroll
    for (int tt = 0; tt < 2; ++tt) {
        int jl = ty * 4 + tt;                // pairs (jl, jl+2): same parity, K-adjacent
        int j  = jt + jl;
        int h  = (j & 1) ? 0 : 1;
        int kp = (j >> 1) >> 1;
        size_t dst = ((size_t)h * KP + kp) * MLDA + kt + tx;
        g_W16c[dst] = packh2(sc[tx][jl], sc[tx][jl + 2]);
        g_W16s[dst] = packh2(ss[tx][jl], ss[tx][jl + 2]);
    }
}

// ---------------- kernel 2: fused reflect-pad + fold + transpose + fp16 pack ----------------
__global__ void __launch_bounds__(256) frame_kernel(const float* __restrict__ x) {
    __shared__ float su[32][33];
    __shared__ float sv[32][33];
    const int b  = blockIdx.z;
    const int t0 = blockIdx.x * 32;
    const int j0 = blockIdx.y * 32;
    const int tx = threadIdx.x & 31;
    const int ty = threadIdx.x >> 5;
    const float* __restrict__ xb = x + (size_t)b * LEN;

#pragma unroll
    for (int tt = 0; tt < 4; ++tt) {
        int tl = ty * 4 + tt;
        int t = t0 + tl;
        float u = 0.f, v = 0.f;
        if (t < NFRAMES) {
            int j = j0 + tx;
            int base = t * HOP - PADW;
            int m1 = base + j + 1;
            int m2 = base + 2047 - j;
            m1 = m1 < 0 ? -m1 : (m1 >= LEN ? 2 * LEN - 2 - m1 : m1);
            m2 = m2 < 0 ? -m2 : (m2 >= LEN ? 2 * LEN - 2 - m2 : m2);
            float a  = xb[m1];
            float bb = xb[m2];
            u = a + bb;
            v = a - bb;
            if (j == 1023) { u = a; v = 0.f; }
        }
        su[tl][tx] = u;
        sv[tl][tx] = v;
    }
    __syncthreads();

    int t = t0 + tx;
    if (t >= NFRAMES) return;
    int bt = b * NFRAMES + t;
#pragma unroll
    for (int tt = 0; tt < 2; ++tt) {
        int jl = ty * 4 + tt;
        int j  = j0 + jl;
        int h  = (j & 1) ? 0 : 1;
        int kp = (j >> 1) >> 1;
        size_t dst = ((size_t)h * KP + kp) * NPAD + bt;
        g_U16[dst] = packh2(su[tx][jl], su[tx][jl + 2]);
        g_V16[dst] = packh2(sv[tx][jl], sv[tx][jl + 2]);
    }
}

// ---------------- kernel 3: exact k=512 row (fp32), one warp per frame ----------------
__global__ void __launch_bounds__(256) k512_kernel(const float* __restrict__ x,
                                                   const float* __restrict__ wcos,
                                                   const float* __restrict__ wsin,
                                                   float* __restrict__ out) {
    __shared__ float wc[NFFT];
    __shared__ float ws[NFFT];
    for (int i = threadIdx.x; i < NFFT; i += 256) {
        wc[i] = wcos[(size_t)512 * NFFT + i];
        ws[i] = wsin[(size_t)512 * NFFT + i];
    }
    __syncthreads();
    const int lane = threadIdx.x & 31;
    const int bt = blockIdx.x * 8 + (threadIdx.x >> 5);
    if (bt >= NBT) return;
    int b = bt / NFRAMES;
    int t = bt - b * NFRAMES;
    const float* __restrict__ xb = x + (size_t)b * LEN;
    int base = t * HOP - PADW;
    float sr = 0.f, si = 0.f;
#pragma unroll 4
    for (int s = lane; s < NFFT; s += 32) {
        int m = base + s;
        m = m < 0 ? -m : (m >= LEN ? 2 * LEN - 2 - m : m);
        float f = xb[m];
        sr += wc[s] * f;
        si += ws[s] * f;
    }
#pragma unroll
    for (int o = 16; o > 0; o >>= 1) {
        sr += __shfl_xor_sync(0xffffffffu, sr, o);
        si += __shfl_xor_sync(0xffffffffu, si, o);
    }
    if (lane == 0) {
        size_t o = (((size_t)b * FREQ + 512) * NFRAMES + t) << 1;
        out[o]     = sr;
        out[o + 1] = -si;
    }
}

// ---------------- kernel 4: FP16 GEMM + fused parity combine ----------------
// CTA 128x64, 4 warps x (64x32), K=512 (rows 0..255 = P+, 256..511 = P-),
// two accumulator sets; epilogue writes out[k] and out[1024-k] directly.
#define MMA_F16(d, a, b)                                                        \
    asm volatile(                                                               \
        "mma.sync.aligned.m16n8k16.row.col.f32.f16.f16.f32 "                    \
        "{%0,%1,%2,%3},{%4,%5,%6,%7},{%8,%9},{%0,%1,%2,%3};"                    \
        : "+f"(d[0]), "+f"(d[1]), "+f"(d[2]), "+f"(d[3])                        \
        : "r"(a[0]), "r"(a[1]), "r"(a[2]), "r"(a[3]), "r"(b[0]), "r"(b[1]))

#define TILE_COMPUTE(ACC)                                                       \
    do {                                                                        \
        _Pragma("unroll")                                                       \
        for (int s = 0; s < 2; ++s) {                                           \
            const int kr0 = 8 * s + tg;                                         \
            const int kr1 = kr0 + 4;                                            \
            uint32_t bf[4][2];                                                  \
            _Pragma("unroll")                                                   \
            for (int j = 0; j < 4; ++j) {                                       \
                bf[j][0] = Bsu[kr0 * BSTR + bbase + 8 * j];                     \
                bf[j][1] = Bsu[kr1 * BSTR + bbase + 8 * j];                     \
            }                                                                   \
            _Pragma("unroll")                                                   \
            for (int i = 0; i < 4; ++i) {                                       \
                uint32_t af[4];                                                 \
                const int mcol = abase + 16 * i;                                \
                af[0] = Asu[kr0 * ASTR + mcol];                                 \
                af[1] = Asu[kr0 * ASTR + mcol + 8];                             \
                af[2] = Asu[kr1 * ASTR + mcol];                                 \
                af[3] = Asu[kr1 * ASTR + mcol + 8];                             \
                _Pragma("unroll")                                               \
                for (int j = 0; j < 4; ++j) MMA_F16(ACC[i][j], af, bf[j]);      \
            }                                                                   \
        }                                                                       \
    } while (0)

__global__ void __launch_bounds__(128, 2) gemm_kernel(float* __restrict__ out) {
    extern __shared__ unsigned smem[];
    const int z = blockIdx.z;                        // 0: cos(real) 1: sin(imag)
    const unsigned* __restrict__ W = z ? g_W16s : g_W16c;
    const unsigned* __restrict__ X = z ? g_V16  : g_U16;

    const int tid  = threadIdx.x;
    const int warp = tid >> 5, lane = tid & 31;
    const int wm = warp & 1;
    const int wn = warp >> 1;
    const int g  = lane >> 2;
    const int tg = lane & 3;
    const int m0 = blockIdx.x * 128;                 // m fast -> B L2 reuse
    const int n0 = blockIdx.y * 64;

    // staging: A 16x128 words (4 f4/thread), B 16x64 words (2 f4/thread)
    const int rA = tid >> 5, cA = (tid & 31) * 4;    // A rows rA+4p
    const int rB = tid >> 4, cB = (tid & 15) * 4;    // B rows rB+8q
    const unsigned* Abase = W + m0 + cA;
    const unsigned* Bbase = X + n0 + cB;

    const uint32_t sbase = (uint32_t)__cvta_generic_to_shared(smem);

    auto issue = [&](int c, int slot) {
        size_t koff = (size_t)c * 16;
        uint32_t sb = sbase + (uint32_t)(slot * STAGE_WORDS * 4);
#pragma unroll
        for (int p = 0; p < 4; ++p) {
            int row = rA + 4 * p;
            cpa16(sb + (uint32_t)((row * ASTR + cA) * 4),
                  Abase + (koff + row) * MLDA);
        }
#pragma unroll
        for (int q = 0; q < 2; ++q) {
            int row = rB + 8 * q;
            cpa16(sb + (uint32_t)((ASZ + row * BSTR + cB) * 4),
                  Bbase + (koff + row) * NPAD);
        }
        cpa_commit();
    };

    float accP[4][4][4], accM[4][4][4];
#pragma unroll
    for (int i = 0; i < 4; ++i)
#pragma unroll
        for (int j = 0; j < 4; ++j)
#pragma unroll
            for (int c = 0; c < 4; ++c) { accP[i][j][c] = 0.f; accM[i][j][c] = 0.f; }

    const int abase = wm * 64 + g;
    const int bbase = wn * 32 + g;

#pragma unroll
    for (int p = 0; p < STAGES - 1; ++p) issue(p, p);

    int slot = 0;
    int islot = STAGES - 1;
    for (int c = 0; c < NKT2; ++c) {
        const int rem = NKT2 - 1 - c;
        if (rem >= 3)      cpa_wait<3>();
        else if (rem == 2) cpa_wait<2>();
        else if (rem == 1) cpa_wait<1>();
        else               cpa_wait<0>();
        __syncthreads();
        if (c + STAGES - 1 < NKT2) issue(c + STAGES - 1, islot);

        const unsigned* Asu = smem + slot * STAGE_WORDS;
        const unsigned* Bsu = Asu + ASZ;
        if (c < NKT2 / 2) TILE_COMPUTE(accP);
        else              TILE_COMPUTE(accM);

        slot  = (slot  == STAGES - 1) ? 0 : slot + 1;
        islot = (islot == STAGES - 1) ? 0 : islot + 1;
    }

    // fused combine epilogue: out[b][k][t][z] and out[b][1024-k][t][z]
#pragma unroll
    for (int i = 0; i < 4; ++i)
#pragma unroll
        for (int h = 0; h < 2; ++h) {
            int k = m0 + wm * 64 + 16 * i + g + 8 * h;    // < 512
#pragma unroll
            for (int j = 0; j < 4; ++j)
#pragma unroll
                for (int q = 0; q < 2; ++q) {
                    int bt = n0 + wn * 32 + 8 * j + 2 * tg + q;
                    if (bt >= NBT) continue;
                    int b = bt / NFRAMES;
                    int t = bt - b * NFRAMES;
                    float rP = accP[i][j][2 * h + q];
                    float rM = accM[i][j][2 * h + q];
                    float s1 = rP + rM;                   // bin k
                    float s2 = rP - rM;                   // bin 1024-k
                    size_t o1 = ((((size_t)b * FREQ + k) * NFRAMES + t) << 1) + z;
                    size_t o2 = ((((size_t)b * FREQ + (1024 - k)) * NFRAMES + t) << 1) + z;
                    out[o1] = z ? -s1 : s1;
                    out[o2] = s2;
                }
        }
}

// ---------------- launch ----------------
extern "C" void kernel_launch(void* const* d_in, const int* in_sizes, int n_in,
                              void* d_out, int out_size) {
    const float* x    = (const float*)d_in[0];
    const float* wcos = (const float*)d_in[1];
    const float* wsin = (const float*)d_in[2];
    float* out = (float*)d_out;

    cudaFuncSetAttribute(gemm_kernel, cudaFuncAttributeMaxDynamicSharedMemorySize, SMEM_BYTES);

    wprep_kernel<<<dim3(1024 / 32, MLDA / 32), 256>>>(wcos, wsin);
    frame_kernel<<<dim3((NFRAMES + 31) / 32, 1024 / 32, BATCH), 256>>>(x);
    k512_kernel<<<(NBT + 7) / 8, 256>>>(x, wcos, wsin, out);
    gemm_kernel<<<dim3(MLDA / 128, NPAD / 64, 2), 128, SMEM_BYTES>>>(out);
}